// round 1
// baseline (speedup 1.0000x reference)
#include <cuda_runtime.h>

// ---------------------------------------------------------------------------
// HiPPO-LegT full-state scan, restructured as parallel GEMMs.
//
//   c_t = A c_{t-1} + B f_t,  c_{-1} = 0,  out[t] = c_t   (t = 0..L-1)
//
// Chunked (C=128, G=16):
//   out[gC+tau] = A^{tau+1} h_g + sum_{j=0..tau} K_j f[t-j]
//   K_j = A^j B,  h_g = state before chunk g,
//   h_g = w_{g-1} + sum_{m=0}^{g-2} (A^C)^{g-1-m} w_m,
//   w_g = sum_{j=0}^{C-1} K_j f[gC+C-1-j].
// ---------------------------------------------------------------------------

#define LSEQ 2048
#define BT   128
#define NST  256
#define CH   128
#define NG   16        // LSEQ / CH
#define NPAIR 105      // sum_{g=2..15} (g-1)

// Scratch (static device memory; no allocations anywhere)
__device__ float g_T[CH * NST * NST];        // g_T[tau] = A^{tau+1}       (33.5 MB)
__device__ float g_P[(NG - 1) * NST * NST];  // g_P[r]   = (A^CH)^{r+1}    (3.9 MB)
__device__ float g_K[CH * NST];              // K_j = A^j B
__device__ float g_w[NG * BT * NST];
__device__ float g_h[NG * BT * NST];
__device__ float g_part[NPAIR * BT * NST];   // Toeplitz partials (13.8 MB)

// ---------------------------------------------------------------------------
__global__ void k_init(const float* __restrict__ A, const float* __restrict__ Bv) {
    int i = blockIdx.x * blockDim.x + threadIdx.x;
    if (i < NST * NST) g_T[i] = A[i];
    if (i < NST)       g_K[i] = Bv[i];   // K_0 = B
}

__global__ void k_copyP() {
    int i = blockIdx.x * blockDim.x + threadIdx.x;
    if (i < NST * NST) g_P[i] = g_T[(CH - 1) * NST * NST + i];
}

// ---------------------------------------------------------------------------
// Stack doubling: out[d+z] = mat[z] @ mat[d-1]   (NN product, 256x256)
// which: 0 -> g_T, 1 -> g_P
// Tile 64x64, 256 threads, 4x4 per thread, k-step 16.
__global__ void k_sqmul(int which, int d) {
    float* base = which ? g_P : g_T;
    int z = blockIdx.z;
    const float* __restrict__ X = base + (size_t)z * NST * NST;
    const float* __restrict__ Y = base + (size_t)(d - 1) * NST * NST;
    float* __restrict__ O = base + (size_t)(d + z) * NST * NST;

    __shared__ float Xs[16][68];   // [m][n]
    __shared__ float Ys[16][68];   // [m][k]
    int tid = threadIdx.x;
    int tx = tid & 15, ty = tid >> 4;
    int n0 = blockIdx.y * 64, k0 = blockIdx.x * 64;
    float acc[4][4];
#pragma unroll
    for (int i = 0; i < 4; i++)
#pragma unroll
        for (int j = 0; j < 4; j++) acc[i][j] = 0.f;

    for (int m0 = 0; m0 < NST; m0 += 16) {
        {   // X tile: 64 rows (n) x 16 cols (m), stored transposed
            int nn = tid >> 2;
            int mb = (tid & 3) * 4;
            float4 v = *(const float4*)&X[(size_t)(n0 + nn) * NST + m0 + mb];
            Xs[mb + 0][nn] = v.x; Xs[mb + 1][nn] = v.y;
            Xs[mb + 2][nn] = v.z; Xs[mb + 3][nn] = v.w;
        }
        {   // Y tile: 16 rows (m) x 64 cols (k), natural
            int mm = tid >> 4;
            int kb = (tid & 15) * 4;
            *(float4*)&Ys[mm][kb] =
                *(const float4*)&Y[(size_t)(m0 + mm) * NST + k0 + kb];
        }
        __syncthreads();
#pragma unroll
        for (int mm = 0; mm < 16; mm++) {
            float a[4], b[4];
            *(float4*)a = *(const float4*)&Xs[mm][ty * 4];
            *(float4*)b = *(const float4*)&Ys[mm][tx * 4];
#pragma unroll
            for (int i = 0; i < 4; i++)
#pragma unroll
                for (int j = 0; j < 4; j++) acc[i][j] += a[i] * b[j];
        }
        __syncthreads();
    }
#pragma unroll
    for (int i = 0; i < 4; i++) {
        float4 v = make_float4(acc[i][0], acc[i][1], acc[i][2], acc[i][3]);
        *(float4*)&O[(size_t)(n0 + ty * 4 + i) * NST + k0 + tx * 4] = v;
    }
}

// ---------------------------------------------------------------------------
// K_j = A^j B = g_T[j-1] @ B, j = 1..CH-1. One block per j, warp per row.
__global__ void k_kern(const float* __restrict__ Bv) {
    int j = blockIdx.x + 1;
    const float* __restrict__ T = g_T + (size_t)(j - 1) * NST * NST;
    __shared__ float Bs[NST];
    int tid = threadIdx.x;
    if (tid < NST) Bs[tid] = Bv[tid];
    __syncthreads();
    int warp = tid >> 5, lane = tid & 31;
    for (int n = warp; n < NST; n += 8) {
        float s = 0.f;
        for (int k = lane; k < NST; k += 32) s += T[(size_t)n * NST + k] * Bs[k];
#pragma unroll
        for (int o = 16; o; o >>= 1) s += __shfl_xor_sync(0xFFFFFFFFu, s, o);
        if (!lane) g_K[j * NST + n] = s;
    }
}

// ---------------------------------------------------------------------------
// w[g][b][n] = sum_{j=0..CH-1} K[j][n] * f[(g*CH + CH-1 - j)*BT + b]
// grid (4 n-tiles, NG), tile 128b x 64n, 256 thr, 8x4 per thread.
__global__ void k_w(const float* __restrict__ f) {
    int g = blockIdx.y;
    int n0 = blockIdx.x * 64;
    __shared__ float Fs[16][132];  // [j][b]
    __shared__ float Ks[16][68];   // [j][n]
    int tid = threadIdx.x;
    int tx = tid & 15, ty = tid >> 4;
    float acc[8][4];
#pragma unroll
    for (int i = 0; i < 8; i++)
#pragma unroll
        for (int j = 0; j < 4; j++) acc[i][j] = 0.f;

    for (int j0 = 0; j0 < CH; j0 += 16) {
        {   // f rows: 16 j x 128 b
            int jj = tid >> 4;
            int cb = (tid & 15) * 8;
            int row = g * CH + CH - 1 - (j0 + jj);
            *(float4*)&Fs[jj][cb]     = *(const float4*)&f[(size_t)row * BT + cb];
            *(float4*)&Fs[jj][cb + 4] = *(const float4*)&f[(size_t)row * BT + cb + 4];
        }
        {   // K rows: 16 j x 64 n
            int jj = tid >> 4;
            int nb = (tid & 15) * 4;
            *(float4*)&Ks[jj][nb] = *(const float4*)&g_K[(j0 + jj) * NST + n0 + nb];
        }
        __syncthreads();
#pragma unroll
        for (int jj = 0; jj < 16; jj++) {
            float a[8], b[4];
            *(float4*)&a[0] = *(const float4*)&Fs[jj][ty * 8];
            *(float4*)&a[4] = *(const float4*)&Fs[jj][ty * 8 + 4];
            *(float4*)b = *(const float4*)&Ks[jj][tx * 4];
#pragma unroll
            for (int i = 0; i < 8; i++)
#pragma unroll
                for (int j = 0; j < 4; j++) acc[i][j] += a[i] * b[j];
        }
        __syncthreads();
    }
#pragma unroll
    for (int i = 0; i < 8; i++) {
        float4 v = make_float4(acc[i][0], acc[i][1], acc[i][2], acc[i][3]);
        *(float4*)&g_w[((size_t)g * BT + ty * 8 + i) * NST + n0 + tx * 4] = v;
    }
}

// ---------------------------------------------------------------------------
// Stage h1: for each pair (g,m): partial[z][b][n] = sum_k w[m][b][k] P[lag][n][k]
// z enumerates (g=2..15, m=0..g-2), lag = g-2-m. Tile 128b x 64n, K=256.
__global__ void k_h1() {
    int z = blockIdx.y;
    int zr = z, g = 2;
    while (zr >= g - 1) { zr -= g - 1; g++; }
    int m = zr;
    int lag = g - 2 - m;

    const float* __restrict__ W = g_w + (size_t)m * BT * NST;
    const float* __restrict__ P = g_P + (size_t)lag * NST * NST;
    float* __restrict__ OUT = g_part + (size_t)blockIdx.y * BT * NST;

    int n0 = blockIdx.x * 64;
    __shared__ float Ws[16][132];  // [k][b]
    __shared__ float Ps[16][68];   // [k][n]
    int tid = threadIdx.x;
    int tx = tid & 15, ty = tid >> 4;
    float acc[8][4];
#pragma unroll
    for (int i = 0; i < 8; i++)
#pragma unroll
        for (int j = 0; j < 4; j++) acc[i][j] = 0.f;

    for (int k0 = 0; k0 < NST; k0 += 16) {
        {   // w tile: 128 b x 16 k, transpose-store
            int b = tid >> 1, kb = (tid & 1) * 8;
            float4 v0 = *(const float4*)&W[(size_t)b * NST + k0 + kb];
            float4 v1 = *(const float4*)&W[(size_t)b * NST + k0 + kb + 4];
            Ws[kb + 0][b] = v0.x; Ws[kb + 1][b] = v0.y;
            Ws[kb + 2][b] = v0.z; Ws[kb + 3][b] = v0.w;
            Ws[kb + 4][b] = v1.x; Ws[kb + 5][b] = v1.y;
            Ws[kb + 6][b] = v1.z; Ws[kb + 7][b] = v1.w;
        }
        {   // P tile: 64 n x 16 k, transpose-store
            int nn = tid >> 2, kb = (tid & 3) * 4;
            float4 v = *(const float4*)&P[(size_t)(n0 + nn) * NST + k0 + kb];
            Ps[kb + 0][nn] = v.x; Ps[kb + 1][nn] = v.y;
            Ps[kb + 2][nn] = v.z; Ps[kb + 3][nn] = v.w;
        }
        __syncthreads();
#pragma unroll
        for (int kk = 0; kk < 16; kk++) {
            float a[8], b[4];
            *(float4*)&a[0] = *(const float4*)&Ws[kk][ty * 8];
            *(float4*)&a[4] = *(const float4*)&Ws[kk][ty * 8 + 4];
            *(float4*)b = *(const float4*)&Ps[kk][tx * 4];
#pragma unroll
            for (int i = 0; i < 8; i++)
#pragma unroll
                for (int j = 0; j < 4; j++) acc[i][j] += a[i] * b[j];
        }
        __syncthreads();
    }
#pragma unroll
    for (int i = 0; i < 8; i++) {
        float4 v = make_float4(acc[i][0], acc[i][1], acc[i][2], acc[i][3]);
        *(float4*)&OUT[(size_t)(ty * 8 + i) * NST + n0 + tx * 4] = v;
    }
}

// Stage h2: h[0]=0; h[1]=w[0]; h[g>=2] = w[g-1] + sum_m partial[(g-1)(g-2)/2 + m]
__global__ void k_h2() {
    int i = blockIdx.x * blockDim.x + threadIdx.x;
    if (i >= NG * BT * NST) return;
    int g = i / (BT * NST);
    int r = i % (BT * NST);
    float v = 0.f;
    if (g >= 1) v = g_w[(size_t)(g - 1) * BT * NST + r];
    if (g >= 2) {
        int base = (g - 1) * (g - 2) / 2;
        for (int m = 0; m <= g - 2; m++)
            v += g_part[(size_t)(base + m) * BT * NST + r];
    }
    g_h[i] = v;
}

// ---------------------------------------------------------------------------
// Main fused kernel: out[t][b][n] = (A^{tau+1} h_g)[b][n] + conv term.
// grid (2048, 2): t, n-half.  Tile 128b x 128n, 256 thr, 8x8 per thread.
__global__ void k_main(const float* __restrict__ f, float* __restrict__ out) {
    int t = blockIdx.x;
    int n0 = blockIdx.y * 128;
    int g = t >> 7;
    int tau = t & (CH - 1);
    int tid = threadIdx.x;
    int tx = tid & 15, ty = tid >> 4;

    __shared__ float As[16][132];  // [k][b]
    __shared__ float Bs[16][132];  // [k][n]
    float acc[8][8];
#pragma unroll
    for (int i = 0; i < 8; i++)
#pragma unroll
        for (int j = 0; j < 8; j++) acc[i][j] = 0.f;

    // ---- Phase 1: boundary term h_g @ (A^{tau+1})^T (skip for g==0) ----
    if (g > 0) {
        const float* __restrict__ H = g_h + (size_t)g * BT * NST;
        const float* __restrict__ T = g_T + (size_t)tau * NST * NST;
        for (int k0 = 0; k0 < NST; k0 += 16) {
            {   // h tile: 128 b x 16 k, transpose
                int b = tid >> 1, kb = (tid & 1) * 8;
                float4 v0 = *(const float4*)&H[(size_t)b * NST + k0 + kb];
                float4 v1 = *(const float4*)&H[(size_t)b * NST + k0 + kb + 4];
                As[kb + 0][b] = v0.x; As[kb + 1][b] = v0.y;
                As[kb + 2][b] = v0.z; As[kb + 3][b] = v0.w;
                As[kb + 4][b] = v1.x; As[kb + 5][b] = v1.y;
                As[kb + 6][b] = v1.z; As[kb + 7][b] = v1.w;
            }
            {   // T tile: 128 n x 16 k, transpose
                int nn = tid >> 1, kb = (tid & 1) * 8;
                float4 v0 = *(const float4*)&T[(size_t)(n0 + nn) * NST + k0 + kb];
                float4 v1 = *(const float4*)&T[(size_t)(n0 + nn) * NST + k0 + kb + 4];
                Bs[kb + 0][nn] = v0.x; Bs[kb + 1][nn] = v0.y;
                Bs[kb + 2][nn] = v0.z; Bs[kb + 3][nn] = v0.w;
                Bs[kb + 4][nn] = v1.x; Bs[kb + 5][nn] = v1.y;
                Bs[kb + 6][nn] = v1.z; Bs[kb + 7][nn] = v1.w;
            }
            __syncthreads();
#pragma unroll
            for (int kk = 0; kk < 16; kk++) {
                float a[8], b[8];
                *(float4*)&a[0] = *(const float4*)&As[kk][ty * 8];
                *(float4*)&a[4] = *(const float4*)&As[kk][ty * 8 + 4];
                *(float4*)&b[0] = *(const float4*)&Bs[kk][tx * 8];
                *(float4*)&b[4] = *(const float4*)&Bs[kk][tx * 8 + 4];
#pragma unroll
                for (int i = 0; i < 8; i++)
#pragma unroll
                    for (int j = 0; j < 8; j++) acc[i][j] += a[i] * b[j];
            }
            __syncthreads();
        }
    }

    // ---- Phase 2: conv term sum_{j<=tau} K[j][n] f[t-j][b] ----
    int nkb = (tau >> 4) + 1;
    for (int kb0 = 0; kb0 < nkb; kb0++) {
        int j0 = kb0 * 16;
        {   // f-Toeplitz tile: [jj][b], masked j<=tau
            int jj = tid >> 4;
            int cb = (tid & 15) * 8;
            int j = j0 + jj;
            float4 v0, v1;
            if (j <= tau) {
                v0 = *(const float4*)&f[(size_t)(t - j) * BT + cb];
                v1 = *(const float4*)&f[(size_t)(t - j) * BT + cb + 4];
            } else {
                v0 = make_float4(0.f, 0.f, 0.f, 0.f);
                v1 = v0;
            }
            *(float4*)&As[jj][cb] = v0;
            *(float4*)&As[jj][cb + 4] = v1;
        }
        {   // K tile: [jj][n]
            int jj = tid >> 4;
            int cb = (tid & 15) * 8;
            int j = j0 + jj;  // always < CH
            *(float4*)&Bs[jj][cb]     = *(const float4*)&g_K[j * NST + n0 + cb];
            *(float4*)&Bs[jj][cb + 4] = *(const float4*)&g_K[j * NST + n0 + cb + 4];
        }
        __syncthreads();
#pragma unroll
        for (int kk = 0; kk < 16; kk++) {
            float a[8], b[8];
            *(float4*)&a[0] = *(const float4*)&As[kk][ty * 8];
            *(float4*)&a[4] = *(const float4*)&As[kk][ty * 8 + 4];
            *(float4*)&b[0] = *(const float4*)&Bs[kk][tx * 8];
            *(float4*)&b[4] = *(const float4*)&Bs[kk][tx * 8 + 4];
#pragma unroll
            for (int i = 0; i < 8; i++)
#pragma unroll
                for (int j = 0; j < 8; j++) acc[i][j] += a[i] * b[j];
        }
        __syncthreads();
    }

    // ---- Epilogue ----
    float* __restrict__ o = out + (size_t)t * BT * NST;
#pragma unroll
    for (int i = 0; i < 8; i++) {
        float4 v0 = make_float4(acc[i][0], acc[i][1], acc[i][2], acc[i][3]);
        float4 v1 = make_float4(acc[i][4], acc[i][5], acc[i][6], acc[i][7]);
        *(float4*)&o[(size_t)(ty * 8 + i) * NST + n0 + tx * 8] = v0;
        *(float4*)&o[(size_t)(ty * 8 + i) * NST + n0 + tx * 8 + 4] = v1;
    }
}

// ---------------------------------------------------------------------------
extern "C" void kernel_launch(void* const* d_in, const int* in_sizes, int n_in,
                              void* d_out, int out_size) {
    const float* f = nullptr;
    const float* A = nullptr;
    const float* Bv = nullptr;
    for (int i = 0; i < n_in; i++) {
        if (in_sizes[i] == LSEQ * BT) f = (const float*)d_in[i];
        else if (in_sizes[i] == NST * NST) A = (const float*)d_in[i];
        else if (in_sizes[i] == NST) Bv = (const float*)d_in[i];
    }
    float* out = (float*)d_out;

    // 1. init: T[0] = A, K[0] = B
    k_init<<<(NST * NST + 255) / 256, 256>>>(A, Bv);

    // 2. T stack doubling: A^1..A^128
    for (int d = 1; d < CH; d <<= 1) {
        int cnt = d;  // d + d <= CH always here
        k_sqmul<<<dim3(4, 4, cnt), 256>>>(0, d);
    }

    // 3. P stack: (A^CH)^1..^(NG-1)
    k_copyP<<<(NST * NST + 255) / 256, 256>>>();
    for (int d = 1; d < NG - 1; d <<= 1) {
        int cnt = (d < (NG - 1 - d)) ? d : (NG - 1 - d);
        k_sqmul<<<dim3(4, 4, cnt), 256>>>(1, d);
    }

    // 4. Conv kernel K_j
    k_kern<<<CH - 1, 256>>>(Bv);

    // 5. Chunk terminal injections w_g
    k_w<<<dim3(4, NG), 256>>>(f);

    // 6. Boundary states h_g (deterministic two-stage Toeplitz combine)
    k_h1<<<dim3(4, NPAIR), 256>>>();
    k_h2<<<(NG * BT * NST + 255) / 256, 256>>>();

    // 7. Main fused output kernel
    k_main<<<dim3(LSEQ, 2), 256>>>(f, out);
    (void)out_size;
}

// round 3
// speedup vs baseline: 2.0611x; 2.0611x over previous
#include <cuda_runtime.h>
#include <cstdint>

// ---------------------------------------------------------------------------
// HiPPO-LegT full-state scan, restructured as parallel GEMMs.
//   c_t = A c_{t-1} + B f_t,  c_{-1} = 0,  out[t] = c_t
// Chunked (C=128, G=16):
//   out[gC+tau] = A^{tau+1} h_g + sum_{j=0..tau} K_j f[t-j]
// Round 3: main kernel on warp-level mma.sync (tf32) — tcgen05 is not
// available in this toolchain (ptxas targets sm_103 without the 'a' feature).
// ---------------------------------------------------------------------------

#define LSEQ 2048
#define BT   128
#define NST  256
#define CH   128
#define NG   16
#define NPAIR 105

__device__ float g_T[CH * NST * NST];        // g_T[tau] = A^{tau+1}
__device__ float g_P[(NG - 1) * NST * NST];  // g_P[r]   = (A^CH)^{r+1}
__device__ float g_K[CH * NST];              // K_j = A^j B   [j][n]
__device__ float g_Kt[NST * CH];             // transposed    [n][j]
__device__ float g_w[NG * BT * NST];
__device__ float g_h[NG * BT * NST];
__device__ float g_part[NPAIR * BT * NST];

// ============================ helpers ======================================
__device__ __forceinline__ uint32_t smem_u32(const void* p) {
    uint32_t a;
    asm("{ .reg .u64 t; cvta.to.shared.u64 t, %1; cvt.u32.u64 %0, t; }"
        : "=r"(a) : "l"(p));
    return a;
}
__device__ __forceinline__ uint32_t f2tf(float x) {
    uint32_t r;
    asm("cvt.rna.tf32.f32 %0, %1;" : "=r"(r) : "f"(x));
    return r;
}
__device__ __forceinline__ void ldsm4(uint32_t addr, uint32_t& r0, uint32_t& r1,
                                      uint32_t& r2, uint32_t& r3) {
    asm volatile("ldmatrix.sync.aligned.m8n8.x4.shared.b16 {%0,%1,%2,%3}, [%4];"
                 : "=r"(r0), "=r"(r1), "=r"(r2), "=r"(r3) : "r"(addr));
}
__device__ __forceinline__ void mma_tf32(float* c, uint32_t a0, uint32_t a1,
                                         uint32_t a2, uint32_t a3,
                                         uint32_t b0, uint32_t b1) {
    asm volatile(
        "mma.sync.aligned.m16n8k8.row.col.f32.tf32.tf32.f32 "
        "{%0,%1,%2,%3}, {%4,%5,%6,%7}, {%8,%9}, {%0,%1,%2,%3};"
        : "+f"(c[0]), "+f"(c[1]), "+f"(c[2]), "+f"(c[3])
        : "r"(a0), "r"(a1), "r"(a2), "r"(a3), "r"(b0), "r"(b1));
}

// ======================= prep kernels (SIMT) ===============================
__global__ void k_init(const float* __restrict__ A, const float* __restrict__ Bv) {
    int i = blockIdx.x * blockDim.x + threadIdx.x;
    if (i < NST * NST) g_T[i] = A[i];
    if (i < NST)       g_K[i] = Bv[i];
}
__global__ void k_copyP() {
    int i = blockIdx.x * blockDim.x + threadIdx.x;
    if (i < NST * NST) g_P[i] = g_T[(CH - 1) * NST * NST + i];
}
__global__ void k_sqmul(int which, int d) {
    float* base = which ? g_P : g_T;
    int z = blockIdx.z;
    const float* __restrict__ X = base + (size_t)z * NST * NST;
    const float* __restrict__ Y = base + (size_t)(d - 1) * NST * NST;
    float* __restrict__ O = base + (size_t)(d + z) * NST * NST;
    __shared__ float Xs[16][68];
    __shared__ float Ys[16][68];
    int tid = threadIdx.x;
    int tx = tid & 15, ty = tid >> 4;
    int n0 = blockIdx.y * 64, k0 = blockIdx.x * 64;
    float acc[4][4];
#pragma unroll
    for (int i = 0; i < 4; i++)
#pragma unroll
        for (int j = 0; j < 4; j++) acc[i][j] = 0.f;
    for (int m0 = 0; m0 < NST; m0 += 16) {
        {
            int nn = tid >> 2;
            int mb = (tid & 3) * 4;
            float4 v = *(const float4*)&X[(size_t)(n0 + nn) * NST + m0 + mb];
            Xs[mb + 0][nn] = v.x; Xs[mb + 1][nn] = v.y;
            Xs[mb + 2][nn] = v.z; Xs[mb + 3][nn] = v.w;
        }
        {
            int mm = tid >> 4;
            int kb = (tid & 15) * 4;
            *(float4*)&Ys[mm][kb] = *(const float4*)&Y[(size_t)(m0 + mm) * NST + k0 + kb];
        }
        __syncthreads();
#pragma unroll
        for (int mm = 0; mm < 16; mm++) {
            float a[4], b[4];
            *(float4*)a = *(const float4*)&Xs[mm][ty * 4];
            *(float4*)b = *(const float4*)&Ys[mm][tx * 4];
#pragma unroll
            for (int i = 0; i < 4; i++)
#pragma unroll
                for (int j = 0; j < 4; j++) acc[i][j] += a[i] * b[j];
        }
        __syncthreads();
    }
#pragma unroll
    for (int i = 0; i < 4; i++) {
        float4 v = make_float4(acc[i][0], acc[i][1], acc[i][2], acc[i][3]);
        *(float4*)&O[(size_t)(n0 + ty * 4 + i) * NST + k0 + tx * 4] = v;
    }
}
__global__ void k_kern(const float* __restrict__ Bv) {
    int j = blockIdx.x + 1;
    const float* __restrict__ T = g_T + (size_t)(j - 1) * NST * NST;
    __shared__ float Bs[NST];
    int tid = threadIdx.x;
    if (tid < NST) Bs[tid] = Bv[tid];
    __syncthreads();
    int warp = tid >> 5, lane = tid & 31;
    for (int n = warp; n < NST; n += 8) {
        float s = 0.f;
        for (int k = lane; k < NST; k += 32) s += T[(size_t)n * NST + k] * Bs[k];
#pragma unroll
        for (int o = 16; o; o >>= 1) s += __shfl_xor_sync(0xFFFFFFFFu, s, o);
        if (!lane) g_K[j * NST + n] = s;
    }
}
__global__ void k_kt() {
    int i = blockIdx.x * blockDim.x + threadIdx.x;
    if (i < CH * NST) {
        int j = i / NST, n = i % NST;
        g_Kt[n * CH + j] = g_K[i];
    }
}
__global__ void k_w(const float* __restrict__ f) {
    int g = blockIdx.y;
    int n0 = blockIdx.x * 64;
    __shared__ float Fs[16][132];
    __shared__ float Ks[16][68];
    int tid = threadIdx.x;
    int tx = tid & 15, ty = tid >> 4;
    float acc[8][4];
#pragma unroll
    for (int i = 0; i < 8; i++)
#pragma unroll
        for (int j = 0; j < 4; j++) acc[i][j] = 0.f;
    for (int j0 = 0; j0 < CH; j0 += 16) {
        {
            int jj = tid >> 4;
            int cb = (tid & 15) * 8;
            int row = g * CH + CH - 1 - (j0 + jj);
            *(float4*)&Fs[jj][cb]     = *(const float4*)&f[(size_t)row * BT + cb];
            *(float4*)&Fs[jj][cb + 4] = *(const float4*)&f[(size_t)row * BT + cb + 4];
        }
        {
            int jj = tid >> 4;
            int nb = (tid & 15) * 4;
            *(float4*)&Ks[jj][nb] = *(const float4*)&g_K[(j0 + jj) * NST + n0 + nb];
        }
        __syncthreads();
#pragma unroll
        for (int jj = 0; jj < 16; jj++) {
            float a[8], b[4];
            *(float4*)&a[0] = *(const float4*)&Fs[jj][ty * 8];
            *(float4*)&a[4] = *(const float4*)&Fs[jj][ty * 8 + 4];
            *(float4*)b = *(const float4*)&Ks[jj][tx * 4];
#pragma unroll
            for (int i = 0; i < 8; i++)
#pragma unroll
                for (int j = 0; j < 4; j++) acc[i][j] += a[i] * b[j];
        }
        __syncthreads();
    }
#pragma unroll
    for (int i = 0; i < 8; i++) {
        float4 v = make_float4(acc[i][0], acc[i][1], acc[i][2], acc[i][3]);
        *(float4*)&g_w[((size_t)g * BT + ty * 8 + i) * NST + n0 + tx * 4] = v;
    }
}
__global__ void k_h1() {
    int z = blockIdx.y;
    int zr = z, g = 2;
    while (zr >= g - 1) { zr -= g - 1; g++; }
    int m = zr;
    int lag = g - 2 - m;
    const float* __restrict__ W = g_w + (size_t)m * BT * NST;
    const float* __restrict__ P = g_P + (size_t)lag * NST * NST;
    float* __restrict__ OUT = g_part + (size_t)blockIdx.y * BT * NST;
    int n0 = blockIdx.x * 64;
    __shared__ float Ws[16][132];
    __shared__ float Ps[16][68];
    int tid = threadIdx.x;
    int tx = tid & 15, ty = tid >> 4;
    float acc[8][4];
#pragma unroll
    for (int i = 0; i < 8; i++)
#pragma unroll
        for (int j = 0; j < 4; j++) acc[i][j] = 0.f;
    for (int k0 = 0; k0 < NST; k0 += 16) {
        {
            int b = tid >> 1, kb = (tid & 1) * 8;
            float4 v0 = *(const float4*)&W[(size_t)b * NST + k0 + kb];
            float4 v1 = *(const float4*)&W[(size_t)b * NST + k0 + kb + 4];
            Ws[kb + 0][b] = v0.x; Ws[kb + 1][b] = v0.y;
            Ws[kb + 2][b] = v0.z; Ws[kb + 3][b] = v0.w;
            Ws[kb + 4][b] = v1.x; Ws[kb + 5][b] = v1.y;
            Ws[kb + 6][b] = v1.z; Ws[kb + 7][b] = v1.w;
        }
        {
            int nn = tid >> 2, kb = (tid & 3) * 4;
            float4 v = *(const float4*)&P[(size_t)(n0 + nn) * NST + k0 + kb];
            Ps[kb + 0][nn] = v.x; Ps[kb + 1][nn] = v.y;
            Ps[kb + 2][nn] = v.z; Ps[kb + 3][nn] = v.w;
        }
        __syncthreads();
#pragma unroll
        for (int kk = 0; kk < 16; kk++) {
            float a[8], b[4];
            *(float4*)&a[0] = *(const float4*)&Ws[kk][ty * 8];
            *(float4*)&a[4] = *(const float4*)&Ws[kk][ty * 8 + 4];
            *(float4*)b = *(const float4*)&Ps[kk][tx * 4];
#pragma unroll
            for (int i = 0; i < 8; i++)
#pragma unroll
                for (int j = 0; j < 4; j++) acc[i][j] += a[i] * b[j];
        }
        __syncthreads();
    }
#pragma unroll
    for (int i = 0; i < 8; i++) {
        float4 v = make_float4(acc[i][0], acc[i][1], acc[i][2], acc[i][3]);
        *(float4*)&OUT[(size_t)(ty * 8 + i) * NST + n0 + tx * 4] = v;
    }
}
__global__ void k_h2() {
    int i = blockIdx.x * blockDim.x + threadIdx.x;
    if (i >= NG * BT * NST) return;
    int g = i / (BT * NST);
    int r = i % (BT * NST);
    float v = 0.f;
    if (g >= 1) v = g_w[(size_t)(g - 1) * BT * NST + r];
    if (g >= 2) {
        int base = (g - 1) * (g - 2) / 2;
        for (int m = 0; m <= g - 2; m++)
            v += g_part[(size_t)(base + m) * BT * NST + r];
    }
    g_h[i] = v;
}

// ======================= main mma.sync kernel ==============================
// One CTA per t. D[128b x 256n] = H_g @ T[tau]^T + F @ Kt^T  in tf32.
// 8 warps, 2(M) x 4(N), warp tile 64x64, mma m16n8k8, ldmatrix fragments.
// SMEM: As 128x32 f32 (16KB), Bs 256x32 f32 (32KB), XOR-swizzled 16B chunks.
#define AS_BYTES 16384
#define SMEM_MAIN (AS_BYTES + 32768)

__device__ __forceinline__ uint32_t sw_off(int row, int k) {
    // row*128 bytes; 8 chunks of 16B per row; chunk ^= row&7
    return (uint32_t)(row * 128 + ((((k >> 2) ^ (row & 7)) << 4) | ((k & 3) << 2)));
}

__global__ void __launch_bounds__(256, 1)
k_main_mma(const float* __restrict__ f, float* __restrict__ out) {
    extern __shared__ char smem[];
    float* As = (float*)smem;
    float* Bs = (float*)(smem + AS_BYTES);
    const uint32_t As_u = smem_u32(As);
    const uint32_t Bs_u = smem_u32(Bs);

    const int tid = threadIdx.x;
    const int lane = tid & 31;
    const int wid = tid >> 5;
    const int wm = wid >> 2;        // 0..1 -> rows 64*wm
    const int wn = wid & 3;         // 0..3 -> cols 64*wn

    const int t = blockIdx.x;
    const int g = t >> 7, tau = t & 127;
    const int p1t = (g > 0) ? 8 : 0;           // 8 k32-tiles for H@T^T (K=256)
    const int p2t = (tau >> 5) + 1;            // 1..4 k32-tiles for conv
    const int nT = p1t + p2t;

    const float* __restrict__ Hrow = g_h + (size_t)g * BT * NST;
    const float* __restrict__ Tm = g_T + (size_t)tau * NST * NST;

    float acc[4][8][4];
#pragma unroll
    for (int mi = 0; mi < 4; mi++)
#pragma unroll
        for (int ni = 0; ni < 8; ni++)
#pragma unroll
            for (int q = 0; q < 4; q++) acc[mi][ni][q] = 0.f;

    // per-thread ldmatrix row indices (fixed across tiles)
    const int a_row = wm * 64 + (lane & 7) + ((lane >> 3) & 1) * 8;   // + mi*16
    const int a_csel = (lane >> 4) & 1;                               // 0/1 -> k +0/+4
    const int b_row = wn * 64 + (lane & 7) + ((lane >> 4) << 3);      // + nb*16
    const int b_csel = (lane >> 3) & 1;                               // 0/1 -> k +0/+4

    for (int it = 0; it < nT; ++it) {
        // ---------------- stage tiles ----------------
        if (it < p1t) {
            int k0 = it * 32;
#pragma unroll
            for (int i = 0; i < 4; i++) {     // A = H : 128 x 32
                int e = tid + i * 256;
                int r = e >> 3, kq = (e & 7) << 2;
                float4 v = *(const float4*)&Hrow[(size_t)r * NST + k0 + kq];
                uint4 w = make_uint4(f2tf(v.x), f2tf(v.y), f2tf(v.z), f2tf(v.w));
                *(uint4*)((char*)As + sw_off(r, kq)) = w;
            }
#pragma unroll
            for (int i = 0; i < 8; i++) {     // B = T : 256 x 32
                int e = tid + i * 256;
                int r = e >> 3, kq = (e & 7) << 2;
                float4 v = *(const float4*)&Tm[(size_t)r * NST + k0 + kq];
                uint4 w = make_uint4(f2tf(v.x), f2tf(v.y), f2tf(v.z), f2tf(v.w));
                *(uint4*)((char*)Bs + sw_off(r, kq)) = w;
            }
        } else {
            int j0 = (it - p1t) * 32;
#pragma unroll
            for (int i = 0; i < 16; i++) {    // A = F (transposed, masked)
                int e = tid + i * 256;
                int b = e & 127, j = e >> 7;  // j in 0..31
                float v = 0.f;
                if (j0 + j <= tau) v = f[(size_t)(t - j0 - j) * BT + b];
                *(uint32_t*)((char*)As + sw_off(b, j)) = f2tf(v);
            }
#pragma unroll
            for (int i = 0; i < 8; i++) {     // B = Kt : 256 x 32
                int e = tid + i * 256;
                int r = e >> 3, kq = (e & 7) << 2;
                float4 v = *(const float4*)&g_Kt[(size_t)r * CH + j0 + kq];
                uint4 w = make_uint4(f2tf(v.x), f2tf(v.y), f2tf(v.z), f2tf(v.w));
                *(uint4*)((char*)Bs + sw_off(r, kq)) = w;
            }
        }
        __syncthreads();

        // ---------------- mainloop: 4 k8-steps ----------------
#pragma unroll
        for (int kt = 0; kt < 4; kt++) {
            uint32_t a[4][4];
#pragma unroll
            for (int mi = 0; mi < 4; mi++) {
                int r = a_row + mi * 16;
                int kc = kt * 8 + a_csel * 4;
                uint32_t addr = As_u + (uint32_t)(r * 128) +
                                ((uint32_t)(((kc >> 2) ^ (r & 7)) << 4));
                ldsm4(addr, a[mi][0], a[mi][1], a[mi][2], a[mi][3]);
            }
            uint32_t b[4][4];
#pragma unroll
            for (int nb = 0; nb < 4; nb++) {
                int r = b_row + nb * 16;
                int kc = kt * 8 + b_csel * 4;
                uint32_t addr = Bs_u + (uint32_t)(r * 128) +
                                ((uint32_t)(((kc >> 2) ^ (r & 7)) << 4));
                ldsm4(addr, b[nb][0], b[nb][1], b[nb][2], b[nb][3]);
            }
#pragma unroll
            for (int mi = 0; mi < 4; mi++)
#pragma unroll
                for (int ni = 0; ni < 8; ni++)
                    mma_tf32(acc[mi][ni], a[mi][0], a[mi][1], a[mi][2], a[mi][3],
                             b[ni >> 1][(ni & 1) * 2], b[ni >> 1][(ni & 1) * 2 + 1]);
        }
        __syncthreads();
    }

    // ---------------- epilogue ----------------
    float* __restrict__ o = out + (size_t)t * BT * NST;
    const int er = wm * 64 + (lane >> 2);
    const int ec0 = wn * 64 + (lane & 3) * 2;
#pragma unroll
    for (int mi = 0; mi < 4; mi++) {
        int r0 = er + mi * 16;
#pragma unroll
        for (int ni = 0; ni < 8; ni++) {
            int c = ec0 + ni * 8;
            *(float2*)&o[(size_t)r0 * NST + c] =
                make_float2(acc[mi][ni][0], acc[mi][ni][1]);
            *(float2*)&o[(size_t)(r0 + 8) * NST + c] =
                make_float2(acc[mi][ni][2], acc[mi][ni][3]);
        }
    }
}

// ---------------------------------------------------------------------------
extern "C" void kernel_launch(void* const* d_in, const int* in_sizes, int n_in,
                              void* d_out, int out_size) {
    const float* f = nullptr;
    const float* A = nullptr;
    const float* Bv = nullptr;
    for (int i = 0; i < n_in; i++) {
        if (in_sizes[i] == LSEQ * BT) f = (const float*)d_in[i];
        else if (in_sizes[i] == NST * NST) A = (const float*)d_in[i];
        else if (in_sizes[i] == NST) Bv = (const float*)d_in[i];
    }
    float* out = (float*)d_out;

    cudaFuncSetAttribute(k_main_mma, cudaFuncAttributeMaxDynamicSharedMemorySize,
                         SMEM_MAIN);

    k_init<<<(NST * NST + 255) / 256, 256>>>(A, Bv);
    for (int d = 1; d < CH; d <<= 1)
        k_sqmul<<<dim3(4, 4, d), 256>>>(0, d);
    k_copyP<<<(NST * NST + 255) / 256, 256>>>();
    for (int d = 1; d < NG - 1; d <<= 1) {
        int cnt = (d < (NG - 1 - d)) ? d : (NG - 1 - d);
        k_sqmul<<<dim3(4, 4, cnt), 256>>>(1, d);
    }
    k_kern<<<CH - 1, 256>>>(Bv);
    k_kt<<<(CH * NST + 255) / 256, 256>>>();
    k_w<<<dim3(4, NG), 256>>>(f);
    k_h1<<<dim3(4, NPAIR), 256>>>();
    k_h2<<<(NG * BT * NST + 255) / 256, 256>>>();

    k_main_mma<<<LSEQ, 256, SMEM_MAIN>>>(f, out);
    (void)out_size;
}

// round 4
// speedup vs baseline: 2.2210x; 1.0776x over previous
#include <cuda_runtime.h>
#include <cstdint>

// ---------------------------------------------------------------------------
// HiPPO-LegT full-state scan as parallel GEMMs (chunked C=128, G=16):
//   out[gC+tau] = A^{tau+1} h_g + sum_{j<=tau} K_j f[t-j]
// Round 4: single flag-synchronized kernel for all matrix powers (fp32),
// tf32 operand pre-conversion, mma.sync h1, cp.async double-buffered main.
// ---------------------------------------------------------------------------

#define LSEQ 2048
#define BT   128
#define NST  256
#define CH   128
#define NG   16
#define NPAIR 105
#define MATSZ (NST * NST)

__device__ float    g_T[CH * MATSZ];          // A^{i+1}, fp32
__device__ uint32_t g_Ttf[CH * MATSZ];        // tf32 copies
__device__ float    g_P[(NG - 1) * MATSZ];    // (A^128)^{r+1}
__device__ uint32_t g_Ptf[(NG - 1) * MATSZ];
__device__ float    g_K[CH * NST];            // K_j = A^j B  [j][n]
__device__ uint32_t g_Kttf[NST * CH];         // tf32, transposed [n][j]
__device__ float    g_w[NG * BT * NST];
__device__ uint32_t g_wtf[NG * BT * NST];
__device__ uint32_t g_htf[NG * BT * NST];
__device__ float    g_part[NPAIR * BT * NST];
__device__ int      g_ready[160];             // per-matrix completion (8 CTAs)

// ============================ helpers ======================================
__device__ __forceinline__ uint32_t smem_u32(const void* p) {
    uint32_t a;
    asm("{ .reg .u64 t; cvta.to.shared.u64 t, %1; cvt.u32.u64 %0, t; }"
        : "=r"(a) : "l"(p));
    return a;
}
__device__ __forceinline__ uint32_t f2tf(float x) {
    uint32_t r;
    asm("cvt.rna.tf32.f32 %0, %1;" : "=r"(r) : "f"(x));
    return r;
}
__device__ __forceinline__ void ldsm4(uint32_t addr, uint32_t& r0, uint32_t& r1,
                                      uint32_t& r2, uint32_t& r3) {
    asm volatile("ldmatrix.sync.aligned.m8n8.x4.shared.b16 {%0,%1,%2,%3}, [%4];"
                 : "=r"(r0), "=r"(r1), "=r"(r2), "=r"(r3) : "r"(addr));
}
__device__ __forceinline__ void mma_tf32(float* c, uint32_t a0, uint32_t a1,
                                         uint32_t a2, uint32_t a3,
                                         uint32_t b0, uint32_t b1) {
    asm volatile(
        "mma.sync.aligned.m16n8k8.row.col.f32.tf32.tf32.f32 "
        "{%0,%1,%2,%3}, {%4,%5,%6,%7}, {%8,%9}, {%0,%1,%2,%3};"
        : "+f"(c[0]), "+f"(c[1]), "+f"(c[2]), "+f"(c[3])
        : "r"(a0), "r"(a1), "r"(a2), "r"(a3), "r"(b0), "r"(b1));
}
#define CP_ASYNC16(dst, src) \
    asm volatile("cp.async.cg.shared.global [%0], [%1], 16;" \
                 :: "r"(dst), "l"(src) : "memory")
#define CP_COMMIT() asm volatile("cp.async.commit_group;" ::: "memory")
#define CP_WAIT1()  asm volatile("cp.async.wait_group 1;" ::: "memory")
#define CP_WAIT0()  asm volatile("cp.async.wait_group 0;" ::: "memory")

// XOR-swizzled byte offset for [row][k] tf32 tiles (32 k per row, 16B chunks)
__device__ __forceinline__ uint32_t sw_off(int row, int k) {
    return (uint32_t)(row * 128 + ((((k >> 2) ^ (row & 7)) << 4) | ((k & 3) << 2)));
}

__device__ __forceinline__ void wait_ready(int id) {
    if (id == 0) return;
    int v;
    do {
        asm volatile("ld.acquire.gpu.global.b32 %0, [%1];"
                     : "=r"(v) : "l"(g_ready + id));
        if (v < 8) __nanosleep(100);
    } while (v < 8);
}

// ============================ k_init =======================================
__global__ void k_init(const float* __restrict__ A, const float* __restrict__ Bv) {
    int i = blockIdx.x * blockDim.x + threadIdx.x;
    if (i < MATSZ) { g_T[i] = A[i]; g_Ttf[i] = f2tf(A[i]); }
    if (i < NST)   { g_K[i] = Bv[i]; g_Kttf[i * CH] = f2tf(Bv[i]); }
    if (i < 160)   g_ready[i] = 0;
}

// ============================ k_powers =====================================
// 142 products x 8 CTAs (128x64 tile each). Matrix ids: 0..127 = T[i]=A^{i+1},
// 128+r = P[r]=(A^128)^{r+1}. Product list (ordered by dependency step):
//   p in [0,127):  d=2^flr(log2(p+1)), z=p+1-d :  T[d+z]=T[z]@T[d-1]
//   p == 127:      copy T[127] -> P[0]
//   p in [128,142): P doubling over r, steps {1,2,4,8}
__global__ void __launch_bounds__(256) k_powers() {
    const int bid = blockIdx.x;
    const int p = bid >> 3, q = bid & 7;
    const int tid = threadIdx.x;

    int xid, yid, oid;
    const float *X = nullptr, *Y = nullptr;
    float *O = nullptr;
    uint32_t *Otf = nullptr;
    bool is_copy = false;

    if (p < 127) {
        int d = 1 << (31 - __clz(p + 1));
        int z = p + 1 - d;
        xid = z; yid = d - 1; oid = d + z;
        X = g_T + (size_t)xid * MATSZ;
        Y = g_T + (size_t)yid * MATSZ;
        O = g_T + (size_t)oid * MATSZ;
        Otf = g_Ttf + (size_t)oid * MATSZ;
    } else if (p == 127) {
        xid = 127; yid = 127; oid = 128;
        is_copy = true;
    } else {
        int p2 = p - 128, d, z;
        if (p2 < 1)      { d = 1; z = 0; }
        else if (p2 < 3) { d = 2; z = p2 - 1; }
        else if (p2 < 7) { d = 4; z = p2 - 3; }
        else             { d = 8; z = p2 - 7; }
        xid = 128 + z; yid = 128 + d - 1; oid = 128 + d + z;
        X = g_P + (size_t)z * MATSZ;
        Y = g_P + (size_t)(d - 1) * MATSZ;
        O = g_P + (size_t)(d + z) * MATSZ;
        Otf = g_Ptf + (size_t)(d + z) * MATSZ;
    }

    if (tid == 0) {
        wait_ready(xid);
        if (yid != xid) wait_ready(yid);
    }
    __syncthreads();

    if (is_copy) {
        const float* S = g_T + (size_t)127 * MATSZ + q * 8192;
        float* D = g_P + q * 8192;
        uint32_t* Dtf = g_Ptf + q * 8192;
        for (int i = tid; i < 2048; i += 256) {
            float4 v = ((const float4*)S)[i];
            ((float4*)D)[i] = v;
            ((uint4*)Dtf)[i] = make_uint4(f2tf(v.x), f2tf(v.y), f2tf(v.z), f2tf(v.w));
        }
    } else {
        const int r0 = (q >> 2) * 128, c0 = (q & 3) * 64;
        __shared__ float Xs[16][132];
        __shared__ float Ys[16][68];
        const int tx = tid & 15, ty = tid >> 4;
        float acc[8][4];
#pragma unroll
        for (int i = 0; i < 8; i++)
#pragma unroll
            for (int j = 0; j < 4; j++) acc[i][j] = 0.f;

        for (int k0 = 0; k0 < NST; k0 += 16) {
            {   // X tile 128x16, transpose-store
                int rr = tid >> 1, kb = (tid & 1) * 8;
                float4 v0 = *(const float4*)&X[(size_t)(r0 + rr) * NST + k0 + kb];
                float4 v1 = *(const float4*)&X[(size_t)(r0 + rr) * NST + k0 + kb + 4];
                Xs[kb + 0][rr] = v0.x; Xs[kb + 1][rr] = v0.y;
                Xs[kb + 2][rr] = v0.z; Xs[kb + 3][rr] = v0.w;
                Xs[kb + 4][rr] = v1.x; Xs[kb + 5][rr] = v1.y;
                Xs[kb + 6][rr] = v1.z; Xs[kb + 7][rr] = v1.w;
            }
            {   // Y tile 16x64, natural
                int kk = tid >> 4, cb = (tid & 15) * 4;
                *(float4*)&Ys[kk][cb] = *(const float4*)&Y[(size_t)(k0 + kk) * NST + c0 + cb];
            }
            __syncthreads();
#pragma unroll
            for (int kk = 0; kk < 16; kk++) {
                float a[8], b[4];
                *(float4*)&a[0] = *(const float4*)&Xs[kk][ty * 8];
                *(float4*)&a[4] = *(const float4*)&Xs[kk][ty * 8 + 4];
                *(float4*)b = *(const float4*)&Ys[kk][tx * 4];
#pragma unroll
                for (int i = 0; i < 8; i++)
#pragma unroll
                    for (int j = 0; j < 4; j++) acc[i][j] += a[i] * b[j];
            }
            __syncthreads();
        }
#pragma unroll
        for (int i = 0; i < 8; i++) {
            size_t idx = (size_t)(r0 + ty * 8 + i) * NST + c0 + tx * 4;
            float4 v = make_float4(acc[i][0], acc[i][1], acc[i][2], acc[i][3]);
            *(float4*)&O[idx] = v;
            *(uint4*)&Otf[idx] = make_uint4(f2tf(v.x), f2tf(v.y), f2tf(v.z), f2tf(v.w));
        }
    }
    __syncthreads();
    if (tid == 0) {
        __threadfence();
        atomicAdd(&g_ready[oid], 1);
    }
}

// ============================ k_kern =======================================
__global__ void k_kern(const float* __restrict__ Bv) {
    int j = blockIdx.x + 1;
    const float* __restrict__ T = g_T + (size_t)(j - 1) * MATSZ;
    __shared__ float Bs[NST];
    int tid = threadIdx.x;
    if (tid < NST) Bs[tid] = Bv[tid];
    __syncthreads();
    int warp = tid >> 5, lane = tid & 31;
    for (int n = warp; n < NST; n += 8) {
        float s = 0.f;
        for (int k = lane; k < NST; k += 32) s += T[(size_t)n * NST + k] * Bs[k];
#pragma unroll
        for (int o = 16; o; o >>= 1) s += __shfl_xor_sync(0xFFFFFFFFu, s, o);
        if (!lane) {
            g_K[j * NST + n] = s;
            g_Kttf[n * CH + j] = f2tf(s);
        }
    }
}

// ============================ k_w ==========================================
__global__ void k_w(const float* __restrict__ f) {
    int g = blockIdx.y;
    int n0 = blockIdx.x * 64;
    __shared__ float Fs[16][132];
    __shared__ float Ks[16][68];
    int tid = threadIdx.x;
    int tx = tid & 15, ty = tid >> 4;
    float acc[8][4];
#pragma unroll
    for (int i = 0; i < 8; i++)
#pragma unroll
        for (int j = 0; j < 4; j++) acc[i][j] = 0.f;
    for (int j0 = 0; j0 < CH; j0 += 16) {
        {
            int jj = tid >> 4;
            int cb = (tid & 15) * 8;
            int row = g * CH + CH - 1 - (j0 + jj);
            *(float4*)&Fs[jj][cb]     = *(const float4*)&f[(size_t)row * BT + cb];
            *(float4*)&Fs[jj][cb + 4] = *(const float4*)&f[(size_t)row * BT + cb + 4];
        }
        {
            int jj = tid >> 4;
            int nb = (tid & 15) * 4;
            *(float4*)&Ks[jj][nb] = *(const float4*)&g_K[(j0 + jj) * NST + n0 + nb];
        }
        __syncthreads();
#pragma unroll
        for (int jj = 0; jj < 16; jj++) {
            float a[8], b[4];
            *(float4*)&a[0] = *(const float4*)&Fs[jj][ty * 8];
            *(float4*)&a[4] = *(const float4*)&Fs[jj][ty * 8 + 4];
            *(float4*)b = *(const float4*)&Ks[jj][tx * 4];
#pragma unroll
            for (int i = 0; i < 8; i++)
#pragma unroll
                for (int j = 0; j < 4; j++) acc[i][j] += a[i] * b[j];
        }
        __syncthreads();
    }
#pragma unroll
    for (int i = 0; i < 8; i++) {
        size_t idx = ((size_t)g * BT + ty * 8 + i) * NST + n0 + tx * 4;
        float4 v = make_float4(acc[i][0], acc[i][1], acc[i][2], acc[i][3]);
        *(float4*)&g_w[idx] = v;
        *(uint4*)&g_wtf[idx] = make_uint4(f2tf(v.x), f2tf(v.y), f2tf(v.z), f2tf(v.w));
    }
}

// ============================ k_h1 (mma tf32) ==============================
// One CTA per pair z: part[z] = W[m] @ P[lag]^T  (M=128, N=256, K=256)
__global__ void __launch_bounds__(256, 1)
k_h1_mma() {
    extern __shared__ char smem[];
    const uint32_t As_u = smem_u32(smem);
    const uint32_t Bs_u = As_u + 16384;

    int z = blockIdx.x;
    int zr = z, g = 2;
    while (zr >= g - 1) { zr -= g - 1; g++; }
    int m = zr;
    int lag = g - 2 - m;

    const uint32_t* __restrict__ W = g_wtf + (size_t)m * BT * NST;
    const uint32_t* __restrict__ P = g_Ptf + (size_t)lag * MATSZ;
    float* __restrict__ OUT = g_part + (size_t)z * BT * NST;

    const int tid = threadIdx.x;
    const int lane = tid & 31;
    const int wid = tid >> 5;
    const int wm = wid >> 2, wn = wid & 3;

    float acc[4][8][4];
#pragma unroll
    for (int mi = 0; mi < 4; mi++)
#pragma unroll
        for (int ni = 0; ni < 8; ni++)
#pragma unroll
            for (int qq = 0; qq < 4; qq++) acc[mi][ni][qq] = 0.f;

    const int a_row = wm * 64 + (lane & 7) + ((lane >> 3) & 1) * 8;
    const int a_csel = (lane >> 4) & 1;
    const int b_row = wn * 64 + (lane & 7) + ((lane >> 4) << 3);
    const int b_csel = (lane >> 3) & 1;

    for (int it = 0; it < 8; ++it) {
        int k0 = it * 32;
#pragma unroll
        for (int i = 0; i < 4; i++) {
            int e = tid + i * 256;
            int r = e >> 3, kq = (e & 7) << 2;
            *(uint4*)(smem + sw_off(r, kq)) = *(const uint4*)&W[(size_t)r * NST + k0 + kq];
        }
#pragma unroll
        for (int i = 0; i < 8; i++) {
            int e = tid + i * 256;
            int r = e >> 3, kq = (e & 7) << 2;
            *(uint4*)(smem + 16384 + sw_off(r, kq)) = *(const uint4*)&P[(size_t)r * NST + k0 + kq];
        }
        __syncthreads();
#pragma unroll
        for (int kt = 0; kt < 4; kt++) {
            uint32_t a[4][4], b[4][4];
#pragma unroll
            for (int mi = 0; mi < 4; mi++) {
                int r = a_row + mi * 16;
                int kc = kt * 8 + a_csel * 4;
                ldsm4(As_u + (uint32_t)(r * 128) + ((uint32_t)(((kc >> 2) ^ (r & 7)) << 4)),
                      a[mi][0], a[mi][1], a[mi][2], a[mi][3]);
            }
#pragma unroll
            for (int nb = 0; nb < 4; nb++) {
                int r = b_row + nb * 16;
                int kc = kt * 8 + b_csel * 4;
                ldsm4(Bs_u + (uint32_t)(r * 128) + ((uint32_t)(((kc >> 2) ^ (r & 7)) << 4)),
                      b[nb][0], b[nb][1], b[nb][2], b[nb][3]);
            }
#pragma unroll
            for (int mi = 0; mi < 4; mi++)
#pragma unroll
                for (int ni = 0; ni < 8; ni++)
                    mma_tf32(acc[mi][ni], a[mi][0], a[mi][1], a[mi][2], a[mi][3],
                             b[ni >> 1][(ni & 1) * 2], b[ni >> 1][(ni & 1) * 2 + 1]);
        }
        __syncthreads();
    }

    const int er = wm * 64 + (lane >> 2);
    const int ec0 = wn * 64 + (lane & 3) * 2;
#pragma unroll
    for (int mi = 0; mi < 4; mi++) {
        int r0 = er + mi * 16;
#pragma unroll
        for (int ni = 0; ni < 8; ni++) {
            int c = ec0 + ni * 8;
            *(float2*)&OUT[(size_t)r0 * NST + c] =
                make_float2(acc[mi][ni][0], acc[mi][ni][1]);
            *(float2*)&OUT[(size_t)(r0 + 8) * NST + c] =
                make_float2(acc[mi][ni][2], acc[mi][ni][3]);
        }
    }
}

// ============================ k_h2 =========================================
__global__ void k_h2() {
    int i = blockIdx.x * blockDim.x + threadIdx.x;
    if (i >= NG * BT * NST) return;
    int g = i / (BT * NST);
    int r = i % (BT * NST);
    float v = 0.f;
    if (g >= 1) v = g_w[(size_t)(g - 1) * BT * NST + r];
    if (g >= 2) {
        int base = (g - 1) * (g - 2) / 2;
        for (int m = 0; m <= g - 2; m++)
            v += g_part[(size_t)(base + m) * BT * NST + r];
    }
    g_htf[i] = f2tf(v);
}

// ============================ k_main =======================================
// One CTA per t, double-buffered cp.async stages (48KB each).
#define AS_BYTES 16384
#define STG_BYTES 49152
#define SMEM_MAIN (2 * STG_BYTES)

__global__ void __launch_bounds__(256, 1)
k_main_mma(const float* __restrict__ f, float* __restrict__ out) {
    extern __shared__ char smem[];
    const uint32_t s0 = smem_u32(smem);

    const int tid = threadIdx.x;
    const int lane = tid & 31;
    const int wid = tid >> 5;
    const int wm = wid >> 2;
    const int wn = wid & 3;

    const int t = blockIdx.x;
    const int g = t >> 7, tau = t & 127;
    const int p1t = (g > 0) ? 8 : 0;
    const int p2t = (tau >> 5) + 1;
    const int nT = p1t + p2t;

    const uint32_t* __restrict__ Htf = g_htf + (size_t)g * BT * NST;
    const uint32_t* __restrict__ Ttf = g_Ttf + (size_t)tau * MATSZ;

    float acc[4][8][4];
#pragma unroll
    for (int mi = 0; mi < 4; mi++)
#pragma unroll
        for (int ni = 0; ni < 8; ni++)
#pragma unroll
            for (int qq = 0; qq < 4; qq++) acc[mi][ni][qq] = 0.f;

    const int a_row = wm * 64 + (lane & 7) + ((lane >> 3) & 1) * 8;
    const int a_csel = (lane >> 4) & 1;
    const int b_row = wn * 64 + (lane & 7) + ((lane >> 4) << 3);
    const int b_csel = (lane >> 3) & 1;

    auto prefetch = [&](int it, int s) {
        uint32_t Au = s0 + (uint32_t)(s * STG_BYTES);
        uint32_t Bu = Au + AS_BYTES;
        if (it < p1t) {
            int k0 = it * 32;
#pragma unroll
            for (int i = 0; i < 4; i++) {
                int e = tid + i * 256;
                int r = e >> 3, kq = (e & 7) << 2;
                CP_ASYNC16(Au + sw_off(r, kq), Htf + (size_t)r * NST + k0 + kq);
            }
#pragma unroll
            for (int i = 0; i < 8; i++) {
                int e = tid + i * 256;
                int r = e >> 3, kq = (e & 7) << 2;
                CP_ASYNC16(Bu + sw_off(r, kq), Ttf + (size_t)r * NST + k0 + kq);
            }
        } else {
            int j0 = (it - p1t) * 32;
#pragma unroll
            for (int i = 0; i < 8; i++) {
                int e = tid + i * 256;
                int r = e >> 3, kq = (e & 7) << 2;
                CP_ASYNC16(Bu + sw_off(r, kq), g_Kttf + (size_t)r * CH + j0 + kq);
            }
#pragma unroll
            for (int i = 0; i < 16; i++) {
                int e = tid + i * 256;
                int b = e & 127, j = e >> 7;
                float v = 0.f;
                if (j0 + j <= tau) v = f[(size_t)(t - j0 - j) * BT + b];
                *(uint32_t*)(smem + s * STG_BYTES + sw_off(b, j)) = f2tf(v);
            }
        }
        CP_COMMIT();
    };

    prefetch(0, 0);
    for (int it = 0; it < nT; ++it) {
        int s = it & 1;
        if (it + 1 < nT) {
            prefetch(it + 1, (it + 1) & 1);
            CP_WAIT1();
        } else {
            CP_WAIT0();
        }
        __syncthreads();

        uint32_t Au = s0 + (uint32_t)(s * STG_BYTES);
        uint32_t Bu = Au + AS_BYTES;
#pragma unroll
        for (int kt = 0; kt < 4; kt++) {
            uint32_t a[4][4], b[4][4];
#pragma unroll
            for (int mi = 0; mi < 4; mi++) {
                int r = a_row + mi * 16;
                int kc = kt * 8 + a_csel * 4;
                ldsm4(Au + (uint32_t)(r * 128) + ((uint32_t)(((kc >> 2) ^ (r & 7)) << 4)),
                      a[mi][0], a[mi][1], a[mi][2], a[mi][3]);
            }
#pragma unroll
            for (int nb = 0; nb < 4; nb++) {
                int r = b_row + nb * 16;
                int kc = kt * 8 + b_csel * 4;
                ldsm4(Bu + (uint32_t)(r * 128) + ((uint32_t)(((kc >> 2) ^ (r & 7)) << 4)),
                      b[nb][0], b[nb][1], b[nb][2], b[nb][3]);
            }
#pragma unroll
            for (int mi = 0; mi < 4; mi++)
#pragma unroll
                for (int ni = 0; ni < 8; ni++)
                    mma_tf32(acc[mi][ni], a[mi][0], a[mi][1], a[mi][2], a[mi][3],
                             b[ni >> 1][(ni & 1) * 2], b[ni >> 1][(ni & 1) * 2 + 1]);
        }
        __syncthreads();
    }

    float* __restrict__ o = out + (size_t)t * BT * NST;
    const int er = wm * 64 + (lane >> 2);
    const int ec0 = wn * 64 + (lane & 3) * 2;
#pragma unroll
    for (int mi = 0; mi < 4; mi++) {
        int r0 = er + mi * 16;
#pragma unroll
        for (int ni = 0; ni < 8; ni++) {
            int c = ec0 + ni * 8;
            *(float2*)&o[(size_t)r0 * NST + c] =
                make_float2(acc[mi][ni][0], acc[mi][ni][1]);
            *(float2*)&o[(size_t)(r0 + 8) * NST + c] =
                make_float2(acc[mi][ni][2], acc[mi][ni][3]);
        }
    }
}

// ---------------------------------------------------------------------------
extern "C" void kernel_launch(void* const* d_in, const int* in_sizes, int n_in,
                              void* d_out, int out_size) {
    const float* f = nullptr;
    const float* A = nullptr;
    const float* Bv = nullptr;
    for (int i = 0; i < n_in; i++) {
        if (in_sizes[i] == LSEQ * BT) f = (const float*)d_in[i];
        else if (in_sizes[i] == NST * NST) A = (const float*)d_in[i];
        else if (in_sizes[i] == NST) Bv = (const float*)d_in[i];
    }
    float* out = (float*)d_out;

    static bool attr_done = false;
    if (!attr_done) {
        cudaFuncSetAttribute(k_main_mma, cudaFuncAttributeMaxDynamicSharedMemorySize,
                             SMEM_MAIN);
        cudaFuncSetAttribute(k_h1_mma, cudaFuncAttributeMaxDynamicSharedMemorySize,
                             STG_BYTES);
        attr_done = true;
    }

    k_init<<<256, 256>>>(A, Bv);
    k_powers<<<142 * 8, 256>>>();
    k_kern<<<CH - 1, 256>>>(Bv);
    k_w<<<dim3(4, NG), 256>>>(f);
    k_h1_mma<<<NPAIR, 256, STG_BYTES>>>();
    k_h2<<<(NG * BT * NST + 255) / 256, 256>>>();
    k_main_mma<<<LSEQ, 256, SMEM_MAIN>>>(f, out);
    (void)out_size;
}